// round 6
// baseline (speedup 1.0000x reference)
#include <cuda_runtime.h>
#include <cuda_fp16.h>
#include <cstdint>

#define N_NODES 100000
#define N_EDGES 2000000
#define DIM     64
#define F_IN    128
#define R_REL   64
#define ER_REL  2048
#define RF_REL  64
#define NCLS    16

// ---------------- scratch (static device memory; no allocations) ----------------
__device__ __align__(16) float g_x0[N_NODES * DIM];        // x2 output of conv2 (fp32)
__device__ __align__(16) __half2 g_x0h[N_NODES * DIM / 2]; // fp16 mirror (proj output)
__device__ __align__(16) __half2 g_x1h[N_NODES * DIM / 2]; // fp16 mirror (conv1 output)
__device__ __align__(16) float g_wrel[R_REL * DIM];        // per-relation edge weights
__device__ int g_cnt[N_NODES];
__device__ int g_cur[N_NODES];
__device__ int g_rowptr[N_NODES + 1];
__device__ unsigned g_eadj[N_EDGES];      // packed (src<<6 | etype), grouped by dst

// ---------------- helpers ----------------
__device__ __forceinline__ void red_add_s32(int* addr, int v) {
    asm volatile("red.global.add.s32 [%0], %1;" :: "l"(addr), "r"(v) : "memory");
}

// ---------------- CSR build ----------------
__global__ void zero_cnt_kernel() {
    int i = blockIdx.x * blockDim.x + threadIdx.x;
    if (i < N_NODES) g_cnt[i] = 0;
}

__global__ void count_kernel(const int* __restrict__ dst) {
    int e = blockIdx.x * blockDim.x + threadIdx.x;
    if (e < N_EDGES) red_add_s32(&g_cnt[dst[e]], 1);
}

__global__ void scan_kernel() {
    __shared__ int ps[1024];
    int tid = threadIdx.x;
    const int CHUNK = 98;  // 1024*98 >= 100000
    int lo = tid * CHUNK;
    int hi = min(lo + CHUNK, N_NODES);
    int sum = 0;
    for (int i = lo; i < hi; ++i) sum += g_cnt[i];
    ps[tid] = sum;
    __syncthreads();
    #pragma unroll
    for (int off = 1; off < 1024; off <<= 1) {
        int v = (tid >= off) ? ps[tid - off] : 0;
        __syncthreads();
        ps[tid] += v;
        __syncthreads();
    }
    int running = ps[tid] - sum;
    for (int i = lo; i < hi; ++i) {
        g_rowptr[i] = running;
        g_cur[i]    = running;
        running += g_cnt[i];
    }
    if (tid == 1023) g_rowptr[N_NODES] = ps[1023];
}

__global__ void fill_kernel(const int* __restrict__ ei,
                            const int* __restrict__ et) {
    int e = blockIdx.x * blockDim.x + threadIdx.x;
    if (e >= N_EDGES) return;
    int s = __ldg(ei + e);
    int d = __ldg(ei + N_EDGES + e);
    int r = __ldg(et + e);
    int pos = atomicAdd(&g_cur[d], 1);
    g_eadj[pos] = ((unsigned)s << 6) | (unsigned)r;
}

// ---------------- relation conv + edge-weight table ----------------
__global__ void rel_kernel(const float* __restrict__ rel_x,
                           const int*   __restrict__ rel_ei,
                           const float* __restrict__ rel_ea,
                           const float* __restrict__ W_nn,
                           const float* __restrict__ b_nn) {
    __shared__ __align__(16) float h[R_REL * RF_REL];
    __shared__ __align__(16) float A[R_REL * R_REL];
    __shared__ float cnt[R_REL];
    int tid = threadIdx.x;  // 1024

    for (int i = tid; i < R_REL * RF_REL; i += 1024) { h[i] = rel_x[i]; A[i] = 0.f; }
    if (tid < R_REL) cnt[tid] = 0.f;
    __syncthreads();

    for (int e = tid; e < ER_REL; e += 1024) {
        int sr = rel_ei[e];
        int dr = rel_ei[ER_REL + e];
        float a = rel_ea[e];
        atomicAdd(&A[dr * R_REL + sr], a);
        atomicAdd(&cnt[dr], 1.0f);
    }
    __syncthreads();

    int r  = tid >> 4;
    int c4 = (tid & 15) * 4;
    float inv = 1.0f / fmaxf(cnt[r], 1.0f);

    #pragma unroll
    for (int it = 0; it < 2; ++it) {
        float4 acc = make_float4(0.f, 0.f, 0.f, 0.f);
        #pragma unroll 8
        for (int k = 0; k < R_REL; ++k) {
            float a = A[r * R_REL + k];
            float4 hv = *(const float4*)&h[k * RF_REL + c4];
            acc.x += a * hv.x; acc.y += a * hv.y;
            acc.z += a * hv.z; acc.w += a * hv.w;
        }
        __syncthreads();
        float4 hv = *(const float4*)&h[r * RF_REL + c4];
        hv.x = fmaxf(hv.x + acc.x * inv, 0.f);
        hv.y = fmaxf(hv.y + acc.y * inv, 0.f);
        hv.z = fmaxf(hv.z + acc.z * inv, 0.f);
        hv.w = fmaxf(hv.w + acc.w * inv, 0.f);
        *(float4*)&h[r * RF_REL + c4] = hv;
        __syncthreads();
    }

    for (int i = tid; i < RF_REL * DIM; i += 1024) A[i] = W_nn[i];
    __syncthreads();
    float4 acc = make_float4(b_nn[c4], b_nn[c4 + 1], b_nn[c4 + 2], b_nn[c4 + 3]);
    #pragma unroll 8
    for (int k = 0; k < RF_REL; ++k) {
        float hv = h[r * RF_REL + k];
        float4 wv = *(const float4*)&A[k * DIM + c4];
        acc.x += hv * wv.x; acc.y += hv * wv.y;
        acc.z += hv * wv.z; acc.w += hv * wv.w;
    }
    *(float4*)&g_wrel[r * DIM + c4] = acc;
}

// x0 = x_in @ fc1 -> fp16 mirror. 128-node tiles, 4 nodes x 8 cols per thread.
__global__ void proj_kernel(const float* __restrict__ x_in,
                            const float* __restrict__ fc1) {
    __shared__ __align__(16) float fs[F_IN * DIM];   // 32 KB
    __shared__ __align__(16) float is[128 * 32];     // 16 KB, swizzled
    int tid = threadIdx.x;  // 256
    for (int i = tid; i < F_IN * DIM; i += 256) fs[i] = fc1[i];

    int c8 = (tid & 7) * 8;
    int n4 = (tid >> 3) * 4;
    int sw = tid >> 3;
    int base = blockIdx.x * 128;

    float acc[4][8];
    #pragma unroll
    for (int j = 0; j < 4; ++j)
        #pragma unroll
        for (int i = 0; i < 8; ++i) acc[j][i] = 0.f;

    #pragma unroll
    for (int kb = 0; kb < F_IN; kb += 32) {
        __syncthreads();
        for (int i = tid; i < 128 * 32; i += 256) {
            int nn = i >> 5, k = i & 31;
            int n = base + nn;
            is[nn * 32 + (k ^ ((nn >> 2) & 31))] =
                (n < N_NODES) ? x_in[(size_t)n * F_IN + kb + k] : 0.f;
        }
        __syncthreads();
        #pragma unroll 4
        for (int kk = 0; kk < 32; ++kk) {
            float4 f0 = *(const float4*)&fs[(kb + kk) * DIM + c8];
            float4 f1 = *(const float4*)&fs[(kb + kk) * DIM + c8 + 4];
            int ks = kk ^ (sw & 31);
            #pragma unroll
            for (int j = 0; j < 4; ++j) {
                float iv = is[(n4 + j) * 32 + ks];
                acc[j][0] += iv * f0.x; acc[j][1] += iv * f0.y;
                acc[j][2] += iv * f0.z; acc[j][3] += iv * f0.w;
                acc[j][4] += iv * f1.x; acc[j][5] += iv * f1.y;
                acc[j][6] += iv * f1.z; acc[j][7] += iv * f1.w;
            }
        }
    }
    #pragma unroll
    for (int j = 0; j < 4; ++j) {
        int n = base + n4 + j;
        if (n < N_NODES) {
            __half2 h0 = __floats2half2_rn(acc[j][0], acc[j][1]);
            __half2 h1 = __floats2half2_rn(acc[j][2], acc[j][3]);
            __half2 h2 = __floats2half2_rn(acc[j][4], acc[j][5]);
            __half2 h3 = __floats2half2_rn(acc[j][6], acc[j][7]);
            uint4 p = make_uint4(*(uint32_t*)&h0, *(uint32_t*)&h1,
                                 *(uint32_t*)&h2, *(uint32_t*)&h3);
            *(uint4*)(g_x0h + (size_t)n * 32 + (c8 >> 1)) = p;
        }
    }
}

// Pull-mode conv, MLP-restored:
//  - 8-lane group per node (uint4 = 16B of the 128B row per lane)
//  - per 8-edge chunk: coalesced eadj load (1 per lane), shfl-broadcast (width 8)
//  - 4 gathers issued back-to-back before FMAs -> MLP 4/group x 4 groups/warp
__device__ __forceinline__ void conv_fma(float acc[8], uint4 p, const float* wrow) {
    float2 a0 = __half22float2(*(__half2*)&p.x);
    float2 a1 = __half22float2(*(__half2*)&p.y);
    float2 a2 = __half22float2(*(__half2*)&p.z);
    float2 a3 = __half22float2(*(__half2*)&p.w);
    float4 w0 = *(const float4*)(wrow);
    float4 w1 = *(const float4*)(wrow + 4);
    acc[0] += a0.x * w0.x; acc[1] += a0.y * w0.y;
    acc[2] += a1.x * w0.z; acc[3] += a1.y * w0.w;
    acc[4] += a2.x * w1.x; acc[5] += a2.y * w1.y;
    acc[6] += a3.x * w1.z; acc[7] += a3.y * w1.w;
}

__global__ void conv_kernel(const float* __restrict__ b, int layer) {
    __shared__ __align__(16) float ws[R_REL * DIM];  // 16 KB
    for (int i = threadIdx.x; i < R_REL * DIM; i += blockDim.x) ws[i] = g_wrel[i];
    __syncthreads();

    const __half2* __restrict__ xh = (layer == 1) ? g_x0h : g_x1h;
    int group = threadIdx.x >> 3;            // 32 groups per 256-thread block
    int lane  = threadIdx.x & 7;
    int n = blockIdx.x * 32 + group;
    if (n >= N_NODES) return;

    int start = __ldg(&g_rowptr[n]);
    int end   = __ldg(&g_rowptr[n + 1]);

    float acc[8];
    #pragma unroll
    for (int i = 0; i < 8; ++i) acc[i] = 0.f;

    const unsigned FULL = 0xffffffffu;

    for (int base = start; base < end; base += 8) {
        int cnt = end - base; if (cnt > 8) cnt = 8;
        unsigned mypk = (base + lane < end) ? __ldg(&g_eadj[base + lane]) : 0u;

        int j = 0;
        for (; j + 4 <= cnt; j += 4) {
            unsigned k0 = __shfl_sync(FULL, mypk, j,     8);
            unsigned k1 = __shfl_sync(FULL, mypk, j + 1, 8);
            unsigned k2 = __shfl_sync(FULL, mypk, j + 2, 8);
            unsigned k3 = __shfl_sync(FULL, mypk, j + 3, 8);
            // issue all 4 gathers before consuming
            uint4 p0 = __ldg((const uint4*)(xh + (size_t)(k0 >> 6) * 32) + lane);
            uint4 p1 = __ldg((const uint4*)(xh + (size_t)(k1 >> 6) * 32) + lane);
            uint4 p2 = __ldg((const uint4*)(xh + (size_t)(k2 >> 6) * 32) + lane);
            uint4 p3 = __ldg((const uint4*)(xh + (size_t)(k3 >> 6) * 32) + lane);
            conv_fma(acc, p0, &ws[(k0 & 63) * DIM + lane * 8]);
            conv_fma(acc, p1, &ws[(k1 & 63) * DIM + lane * 8]);
            conv_fma(acc, p2, &ws[(k2 & 63) * DIM + lane * 8]);
            conv_fma(acc, p3, &ws[(k3 & 63) * DIM + lane * 8]);
        }
        for (; j < cnt; ++j) {
            unsigned k0 = __shfl_sync(FULL, mypk, j, 8);
            uint4 p0 = __ldg((const uint4*)(xh + (size_t)(k0 >> 6) * 32) + lane);
            conv_fma(acc, p0, &ws[(k0 & 63) * DIM + lane * 8]);
        }
    }

    int deg = end - start;
    float inv = 1.0f / (float)(deg > 0 ? deg : 1);
    float bb[8];
    *(float4*)&bb[0] = *(const float4*)(b + lane * 8);
    *(float4*)&bb[4] = *(const float4*)(b + lane * 8 + 4);
    float v[8];
    #pragma unroll
    for (int i = 0; i < 8; ++i) v[i] = tanhf(acc[i] * inv + bb[i]);

    if (layer == 1) {
        __half2 h0 = __floats2half2_rn(v[0], v[1]);
        __half2 h1 = __floats2half2_rn(v[2], v[3]);
        __half2 h2 = __floats2half2_rn(v[4], v[5]);
        __half2 h3 = __floats2half2_rn(v[6], v[7]);
        uint4 p = make_uint4(*(uint32_t*)&h0, *(uint32_t*)&h1,
                             *(uint32_t*)&h2, *(uint32_t*)&h3);
        *((uint4*)(g_x1h + (size_t)n * 32) + lane) = p;
    } else {
        *(float4*)&g_x0[(size_t)n * DIM + lane * 8]     = *(float4*)&v[0];
        *(float4*)&g_x0[(size_t)n * DIM + lane * 8 + 4] = *(float4*)&v[4];
    }
}

// out = x2 @ fc2_w + fc2_b   (x2 in g_x0).  16 nodes per block.
__global__ void out_kernel(const float* __restrict__ fc2w,
                           const float* __restrict__ fc2b,
                           float* __restrict__ out) {
    __shared__ float ws[DIM * NCLS];
    __shared__ float xs[16 * DIM];
    int tid = threadIdx.x;
    for (int i = tid; i < DIM * NCLS; i += 256) ws[i] = fc2w[i];
    int base = blockIdx.x * 16;
    for (int i = tid; i < 16 * DIM; i += 256) xs[i] = g_x0[(size_t)base * DIM + i];
    __syncthreads();
    int nl = tid >> 4, k = tid & 15;
    float acc = fc2b[k];
    #pragma unroll
    for (int c = 0; c < DIM; ++c)
        acc += xs[nl * DIM + c] * ws[c * NCLS + k];
    out[(size_t)(base + nl) * NCLS + k] = acc;
}

// ---------------- launch ----------------
extern "C" void kernel_launch(void* const* d_in, const int* in_sizes, int n_in,
                              void* d_out, int out_size) {
    const float* x_in   = (const float*)d_in[0];
    const float* rel_x  = (const float*)d_in[1];
    const int*   ei     = (const int*)  d_in[2];
    const int*   et     = (const int*)  d_in[3];
    const int*   rel_ei = (const int*)  d_in[4];
    const float* rel_ea = (const float*)d_in[5];
    const float* fc1    = (const float*)d_in[6];
    const float* W_nn   = (const float*)d_in[7];
    const float* b_nn   = (const float*)d_in[8];
    const float* b1     = (const float*)d_in[9];
    const float* b2     = (const float*)d_in[10];
    const float* fc2w   = (const float*)d_in[11];
    const float* fc2b   = (const float*)d_in[12];
    float* out = (float*)d_out;

    zero_cnt_kernel<<<(N_NODES + 255) / 256, 256>>>();
    count_kernel<<<(N_EDGES + 255) / 256, 256>>>(ei + N_EDGES);
    scan_kernel<<<1, 1024>>>();
    fill_kernel<<<(N_EDGES + 255) / 256, 256>>>(ei, et);

    rel_kernel<<<1, 1024>>>(rel_x, rel_ei, rel_ea, W_nn, b_nn);
    proj_kernel<<<(N_NODES + 127) / 128, 256>>>(x_in, fc1);

    conv_kernel<<<(N_NODES + 31) / 32, 256>>>(b1, 1);   // x1 (fp16 mirror)
    conv_kernel<<<(N_NODES + 31) / 32, 256>>>(b2, 2);   // x2 (fp32 into g_x0)

    out_kernel<<<N_NODES / 16, 256>>>(fc2w, fc2b, out);
}

// round 7
// speedup vs baseline: 1.0254x; 1.0254x over previous
#include <cuda_runtime.h>
#include <cuda_fp16.h>
#include <cstdint>

#define N_NODES 100000
#define N_EDGES 2000000
#define DIM     64
#define F_IN    128
#define R_REL   64
#define ER_REL  2048
#define RF_REL  64
#define NCLS    16
#define CHUNK   64   // edges per 8-lane group in the sweep (2M/64 = 31250 groups)

// ---------------- scratch (static device memory; no allocations) ----------------
__device__ __align__(16) float g_x0[N_NODES * DIM];        // x2 output of conv2 (fp32)
__device__ __align__(16) float g_agg[N_NODES * DIM];       // scatter accumulator
__device__ __align__(16) __half2 g_x0h[N_NODES * DIM / 2]; // fp16 mirror (proj output)
__device__ __align__(16) __half2 g_x1h[N_NODES * DIM / 2]; // fp16 mirror (conv1 output)
__device__ __align__(16) float g_wrel[R_REL * DIM];        // per-relation edge weights
__device__ int g_cnt[N_NODES];                             // degree (by dst)
__device__ int g_cur[N_NODES];                             // fill cursors
__device__ int g_rowptr[N_NODES + 1];
__device__ __align__(16) unsigned long long g_eadj64[N_EDGES]; // (src<<23)|(et<<17)|dst, sorted by dst

// ---------------- helpers ----------------
__device__ __forceinline__ void red_add_v4(float* addr, float a, float b, float c, float d) {
    asm volatile("red.global.add.v4.f32 [%0], {%1, %2, %3, %4};"
                 :: "l"(addr), "f"(a), "f"(b), "f"(c), "f"(d)
                 : "memory");
}
__device__ __forceinline__ void red_add_s32(int* addr, int v) {
    asm volatile("red.global.add.s32 [%0], %1;" :: "l"(addr), "r"(v) : "memory");
}

// ---------------- CSR-sort build ----------------
__global__ void zero_kernel() {
    int i = blockIdx.x * blockDim.x + threadIdx.x;
    if (i < N_NODES * DIM / 4) ((float4*)g_agg)[i] = make_float4(0.f, 0.f, 0.f, 0.f);
    if (i < N_NODES) g_cnt[i] = 0;
}

__global__ void count_kernel(const int* __restrict__ dst) {
    int e = blockIdx.x * blockDim.x + threadIdx.x;
    if (e < N_EDGES) red_add_s32(&g_cnt[dst[e]], 1);
}

__global__ void scan_kernel() {
    __shared__ int ps[1024];
    int tid = threadIdx.x;
    const int CH = 98;  // 1024*98 >= 100000
    int lo = tid * CH;
    int hi = min(lo + CH, N_NODES);
    int sum = 0;
    for (int i = lo; i < hi; ++i) sum += g_cnt[i];
    ps[tid] = sum;
    __syncthreads();
    #pragma unroll
    for (int off = 1; off < 1024; off <<= 1) {
        int v = (tid >= off) ? ps[tid - off] : 0;
        __syncthreads();
        ps[tid] += v;
        __syncthreads();
    }
    int running = ps[tid] - sum;
    for (int i = lo; i < hi; ++i) {
        g_rowptr[i] = running;
        g_cur[i]    = running;
        running += g_cnt[i];
    }
    if (tid == 1023) g_rowptr[N_NODES] = ps[1023];
}

__global__ void fill_kernel(const int* __restrict__ ei,
                            const int* __restrict__ et) {
    int e = blockIdx.x * blockDim.x + threadIdx.x;
    if (e >= N_EDGES) return;
    int s = __ldg(ei + e);
    int d = __ldg(ei + N_EDGES + e);
    int r = __ldg(et + e);
    int pos = atomicAdd(&g_cur[d], 1);
    g_eadj64[pos] = ((unsigned long long)(unsigned)s << 23)
                  | ((unsigned long long)(unsigned)r << 17)
                  | (unsigned long long)(unsigned)d;
}

// ---------------- relation conv + edge-weight table ----------------
__global__ void rel_kernel(const float* __restrict__ rel_x,
                           const int*   __restrict__ rel_ei,
                           const float* __restrict__ rel_ea,
                           const float* __restrict__ W_nn,
                           const float* __restrict__ b_nn) {
    __shared__ __align__(16) float h[R_REL * RF_REL];
    __shared__ __align__(16) float A[R_REL * R_REL];
    __shared__ float cnt[R_REL];
    int tid = threadIdx.x;  // 1024

    for (int i = tid; i < R_REL * RF_REL; i += 1024) { h[i] = rel_x[i]; A[i] = 0.f; }
    if (tid < R_REL) cnt[tid] = 0.f;
    __syncthreads();

    for (int e = tid; e < ER_REL; e += 1024) {
        int sr = rel_ei[e];
        int dr = rel_ei[ER_REL + e];
        float a = rel_ea[e];
        atomicAdd(&A[dr * R_REL + sr], a);
        atomicAdd(&cnt[dr], 1.0f);
    }
    __syncthreads();

    int r  = tid >> 4;
    int c4 = (tid & 15) * 4;
    float inv = 1.0f / fmaxf(cnt[r], 1.0f);

    #pragma unroll
    for (int it = 0; it < 2; ++it) {
        float4 acc = make_float4(0.f, 0.f, 0.f, 0.f);
        #pragma unroll 8
        for (int k = 0; k < R_REL; ++k) {
            float a = A[r * R_REL + k];
            float4 hv = *(const float4*)&h[k * RF_REL + c4];
            acc.x += a * hv.x; acc.y += a * hv.y;
            acc.z += a * hv.z; acc.w += a * hv.w;
        }
        __syncthreads();
        float4 hv = *(const float4*)&h[r * RF_REL + c4];
        hv.x = fmaxf(hv.x + acc.x * inv, 0.f);
        hv.y = fmaxf(hv.y + acc.y * inv, 0.f);
        hv.z = fmaxf(hv.z + acc.z * inv, 0.f);
        hv.w = fmaxf(hv.w + acc.w * inv, 0.f);
        *(float4*)&h[r * RF_REL + c4] = hv;
        __syncthreads();
    }

    for (int i = tid; i < RF_REL * DIM; i += 1024) A[i] = W_nn[i];
    __syncthreads();
    float4 acc = make_float4(b_nn[c4], b_nn[c4 + 1], b_nn[c4 + 2], b_nn[c4 + 3]);
    #pragma unroll 8
    for (int k = 0; k < RF_REL; ++k) {
        float hv = h[r * RF_REL + k];
        float4 wv = *(const float4*)&A[k * DIM + c4];
        acc.x += hv * wv.x; acc.y += hv * wv.y;
        acc.z += hv * wv.z; acc.w += hv * wv.w;
    }
    *(float4*)&g_wrel[r * DIM + c4] = acc;
}

// x0 = x_in @ fc1 -> fp16 mirror. 128-node tiles, 4 nodes x 8 cols per thread.
__global__ void proj_kernel(const float* __restrict__ x_in,
                            const float* __restrict__ fc1) {
    __shared__ __align__(16) float fs[F_IN * DIM];   // 32 KB
    __shared__ __align__(16) float is[128 * 32];     // 16 KB, swizzled
    int tid = threadIdx.x;  // 256
    for (int i = tid; i < F_IN * DIM; i += 256) fs[i] = fc1[i];

    int c8 = (tid & 7) * 8;
    int n4 = (tid >> 3) * 4;
    int sw = tid >> 3;
    int base = blockIdx.x * 128;

    float acc[4][8];
    #pragma unroll
    for (int j = 0; j < 4; ++j)
        #pragma unroll
        for (int i = 0; i < 8; ++i) acc[j][i] = 0.f;

    #pragma unroll
    for (int kb = 0; kb < F_IN; kb += 32) {
        __syncthreads();
        for (int i = tid; i < 128 * 32; i += 256) {
            int nn = i >> 5, k = i & 31;
            int n = base + nn;
            is[nn * 32 + (k ^ ((nn >> 2) & 31))] =
                (n < N_NODES) ? x_in[(size_t)n * F_IN + kb + k] : 0.f;
        }
        __syncthreads();
        #pragma unroll 4
        for (int kk = 0; kk < 32; ++kk) {
            float4 f0 = *(const float4*)&fs[(kb + kk) * DIM + c8];
            float4 f1 = *(const float4*)&fs[(kb + kk) * DIM + c8 + 4];
            int ks = kk ^ (sw & 31);
            #pragma unroll
            for (int j = 0; j < 4; ++j) {
                float iv = is[(n4 + j) * 32 + ks];
                acc[j][0] += iv * f0.x; acc[j][1] += iv * f0.y;
                acc[j][2] += iv * f0.z; acc[j][3] += iv * f0.w;
                acc[j][4] += iv * f1.x; acc[j][5] += iv * f1.y;
                acc[j][6] += iv * f1.z; acc[j][7] += iv * f1.w;
            }
        }
    }
    #pragma unroll
    for (int j = 0; j < 4; ++j) {
        int n = base + n4 + j;
        if (n < N_NODES) {
            __half2 h0 = __floats2half2_rn(acc[j][0], acc[j][1]);
            __half2 h1 = __floats2half2_rn(acc[j][2], acc[j][3]);
            __half2 h2 = __floats2half2_rn(acc[j][4], acc[j][5]);
            __half2 h3 = __floats2half2_rn(acc[j][6], acc[j][7]);
            uint4 p = make_uint4(*(uint32_t*)&h0, *(uint32_t*)&h1,
                                 *(uint32_t*)&h2, *(uint32_t*)&h3);
            *(uint4*)(g_x0h + (size_t)n * 32 + (c8 >> 1)) = p;
        }
    }
}

// ---------------- segmented push sweep ----------------
// 8-lane group processes CHUNK consecutive dst-sorted edges. Register
// accumulation within a dst-run; RED flush only on run change / chunk end.
__device__ __forceinline__ void sweep_fma(float acc[8], uint4 p, const float* wrow) {
    float2 a0 = __half22float2(*(__half2*)&p.x);
    float2 a1 = __half22float2(*(__half2*)&p.y);
    float2 a2 = __half22float2(*(__half2*)&p.z);
    float2 a3 = __half22float2(*(__half2*)&p.w);
    float4 w0 = *(const float4*)(wrow);
    float4 w1 = *(const float4*)(wrow + 4);
    acc[0] += a0.x * w0.x; acc[1] += a0.y * w0.y;
    acc[2] += a1.x * w0.z; acc[3] += a1.y * w0.w;
    acc[4] += a2.x * w1.x; acc[5] += a2.y * w1.y;
    acc[6] += a3.x * w1.z; acc[7] += a3.y * w1.w;
}

__global__ void sweep_kernel(int layer) {
    __shared__ __align__(16) float ws[R_REL * DIM];  // 16 KB
    for (int i = threadIdx.x; i < R_REL * DIM; i += blockDim.x) ws[i] = g_wrel[i];
    __syncthreads();

    const __half2* __restrict__ xh = (layer == 1) ? g_x0h : g_x1h;
    int group = (blockIdx.x * blockDim.x + threadIdx.x) >> 3;
    int lane  = threadIdx.x & 7;
    if (group >= N_EDGES / CHUNK) return;
    size_t base = (size_t)group * CHUNK;

    float acc[8];
    #pragma unroll
    for (int i = 0; i < 8; ++i) acc[i] = 0.f;
    int cur = -1;

    for (int i = 0; i < CHUNK; i += 4) {
        ulonglong2 q0 = __ldg((const ulonglong2*)(g_eadj64 + base + i));
        ulonglong2 q1 = __ldg((const ulonglong2*)(g_eadj64 + base + i + 2));
        unsigned long long e0 = q0.x, e1 = q0.y, e2 = q1.x, e3 = q1.y;
        // issue all 4 gathers before consuming any
        uint4 p0 = __ldg((const uint4*)(xh + (size_t)(e0 >> 23) * 32) + lane);
        uint4 p1 = __ldg((const uint4*)(xh + (size_t)(e1 >> 23) * 32) + lane);
        uint4 p2 = __ldg((const uint4*)(xh + (size_t)(e2 >> 23) * 32) + lane);
        uint4 p3 = __ldg((const uint4*)(xh + (size_t)(e3 >> 23) * 32) + lane);

        unsigned long long es[4] = {e0, e1, e2, e3};
        uint4 ps[4] = {p0, p1, p2, p3};
        #pragma unroll
        for (int j = 0; j < 4; ++j) {
            int d = (int)(es[j] & 0x1FFFF);
            if (d != cur) {
                if (cur >= 0) {
                    float* a = g_agg + (size_t)cur * DIM + lane * 8;
                    red_add_v4(a,     acc[0], acc[1], acc[2], acc[3]);
                    red_add_v4(a + 4, acc[4], acc[5], acc[6], acc[7]);
                }
                #pragma unroll
                for (int t = 0; t < 8; ++t) acc[t] = 0.f;
                cur = d;
            }
            sweep_fma(acc, ps[j], &ws[((unsigned)(es[j] >> 17) & 63u) * DIM + lane * 8]);
        }
    }
    // final flush
    float* a = g_agg + (size_t)cur * DIM + lane * 8;
    red_add_v4(a,     acc[0], acc[1], acc[2], acc[3]);
    red_add_v4(a + 4, acc[4], acc[5], acc[6], acc[7]);
}

// x_out = tanh(agg / max(deg,1) + b). float4 per thread.
__global__ void finish_kernel(const float* __restrict__ b,
                              int layer, int zero_agg) {
    int i = blockIdx.x * blockDim.x + threadIdx.x;
    if (i >= N_NODES * (DIM / 4)) return;
    int n = i >> 4, c4 = (i & 15) * 4;
    float4 v = ((const float4*)g_agg)[i];
    int d = g_cnt[n];
    float inv = 1.0f / (float)(d > 0 ? d : 1);
    float4 bb = *(const float4*)(b + c4);
    v.x = tanhf(v.x * inv + bb.x);
    v.y = tanhf(v.y * inv + bb.y);
    v.z = tanhf(v.z * inv + bb.z);
    v.w = tanhf(v.w * inv + bb.w);
    if (layer == 1) {
        __half2 h0 = __floats2half2_rn(v.x, v.y);
        __half2 h1 = __floats2half2_rn(v.z, v.w);
        uint2 p = make_uint2(*(uint32_t*)&h0, *(uint32_t*)&h1);
        *(uint2*)(g_x1h + (size_t)n * 32 + (c4 >> 1)) = p;
    } else {
        ((float4*)g_x0)[i] = v;
    }
    if (zero_agg) ((float4*)g_agg)[i] = make_float4(0.f, 0.f, 0.f, 0.f);
}

// out = x2 @ fc2_w + fc2_b   (x2 in g_x0).  16 nodes per block.
__global__ void out_kernel(const float* __restrict__ fc2w,
                           const float* __restrict__ fc2b,
                           float* __restrict__ out) {
    __shared__ float ws[DIM * NCLS];
    __shared__ float xs[16 * DIM];
    int tid = threadIdx.x;
    for (int i = tid; i < DIM * NCLS; i += 256) ws[i] = fc2w[i];
    int base = blockIdx.x * 16;
    for (int i = tid; i < 16 * DIM; i += 256) xs[i] = g_x0[(size_t)base * DIM + i];
    __syncthreads();
    int nl = tid >> 4, k = tid & 15;
    float acc = fc2b[k];
    #pragma unroll
    for (int c = 0; c < DIM; ++c)
        acc += xs[nl * DIM + c] * ws[c * NCLS + k];
    out[(size_t)(base + nl) * NCLS + k] = acc;
}

// ---------------- launch ----------------
extern "C" void kernel_launch(void* const* d_in, const int* in_sizes, int n_in,
                              void* d_out, int out_size) {
    const float* x_in   = (const float*)d_in[0];
    const float* rel_x  = (const float*)d_in[1];
    const int*   ei     = (const int*)  d_in[2];
    const int*   et     = (const int*)  d_in[3];
    const int*   rel_ei = (const int*)  d_in[4];
    const float* rel_ea = (const float*)d_in[5];
    const float* fc1    = (const float*)d_in[6];
    const float* W_nn   = (const float*)d_in[7];
    const float* b_nn   = (const float*)d_in[8];
    const float* b1     = (const float*)d_in[9];
    const float* b2     = (const float*)d_in[10];
    const float* fc2w   = (const float*)d_in[11];
    const float* fc2b   = (const float*)d_in[12];
    float* out = (float*)d_out;

    // build dst-sorted edge list (+ degree counts, zeroed agg)
    zero_kernel<<<(N_NODES * DIM / 4 + 255) / 256, 256>>>();
    count_kernel<<<(N_EDGES + 255) / 256, 256>>>(ei + N_EDGES);
    scan_kernel<<<1, 1024>>>();
    fill_kernel<<<(N_EDGES + 255) / 256, 256>>>(ei, et);

    rel_kernel<<<1, 1024>>>(rel_x, rel_ei, rel_ea, W_nn, b_nn);
    proj_kernel<<<(N_NODES + 127) / 128, 256>>>(x_in, fc1);

    const int NGROUPS = N_EDGES / CHUNK;             // 31250
    const int SWEEP_BLOCKS = (NGROUPS * 8 + 255) / 256;

    sweep_kernel<<<SWEEP_BLOCKS, 256>>>(1);
    finish_kernel<<<(N_NODES * 16 + 255) / 256, 256>>>(b1, 1, /*zero_agg=*/1);

    sweep_kernel<<<SWEEP_BLOCKS, 256>>>(2);
    finish_kernel<<<(N_NODES * 16 + 255) / 256, 256>>>(b2, 2, /*zero_agg=*/0);

    out_kernel<<<N_NODES / 16, 256>>>(fc2w, fc2b, out);
}

// round 8
// speedup vs baseline: 1.4115x; 1.3765x over previous
#include <cuda_runtime.h>
#include <cuda_fp16.h>
#include <cstdint>

#define N_NODES 100000
#define N_EDGES 2000000
#define DIM     64
#define F_IN    128
#define R_REL   64
#define ER_REL  2048
#define RF_REL  64
#define NCLS    16

// ---------------- scratch (static device memory; no allocations) ----------------
__device__ __align__(16) float g_x0[N_NODES * DIM];        // x2 (fp32, for out_kernel)
__device__ __align__(16) float g_agg[N_NODES * DIM];       // scatter accumulator
__device__ __align__(16) __half2 g_x0h[N_NODES * DIM / 2]; // fp16 mirror of x0 (proj out)
__device__ __align__(16) __half2 g_x1h[N_NODES * DIM / 2]; // fp16 mirror of x1 (conv1 out)
__device__ int g_deg[N_NODES];
__device__ __align__(16) float g_wrel[R_REL * DIM];        // per-relation edge weights
__device__ __align__(16) unsigned g_pk[N_EDGES];           // packed (src<<6)|etype

// ---------------- helpers ----------------
__device__ __forceinline__ void red_add_v4(float* addr, float a, float b, float c, float d) {
    asm volatile("red.global.add.v4.f32 [%0], {%1, %2, %3, %4};"
                 :: "l"(addr), "f"(a), "f"(b), "f"(c), "f"(d)
                 : "memory");
}
__device__ __forceinline__ void red_add_s32(int* addr, int v) {
    asm volatile("red.global.add.s32 [%0], %1;" :: "l"(addr), "r"(v) : "memory");
}

// ---------------- kernels ----------------
__global__ void zero_kernel() {
    int i = blockIdx.x * blockDim.x + threadIdx.x;
    if (i < N_NODES * DIM / 4) ((float4*)g_agg)[i] = make_float4(0.f, 0.f, 0.f, 0.f);
    if (i < N_NODES) g_deg[i] = 0;
}

// Pack (src<<6 | etype) once; reused by both sweeps.
__global__ void pack_kernel(const int* __restrict__ src,
                            const int* __restrict__ et) {
    int e = blockIdx.x * blockDim.x + threadIdx.x;
    if (e < N_EDGES)
        g_pk[e] = ((unsigned)__ldg(src + e) << 6) | (unsigned)__ldg(et + e);
}

// Relation conv x2 + w_rel = relu-chain(rel_x) @ W_nn + b_nn (GEMM form).
__global__ void rel_kernel(const float* __restrict__ rel_x,
                           const int*   __restrict__ rel_ei,
                           const float* __restrict__ rel_ea,
                           const float* __restrict__ W_nn,
                           const float* __restrict__ b_nn) {
    __shared__ __align__(16) float h[R_REL * RF_REL];
    __shared__ __align__(16) float A[R_REL * R_REL];
    __shared__ float cnt[R_REL];
    int tid = threadIdx.x;  // 1024

    for (int i = tid; i < R_REL * RF_REL; i += 1024) { h[i] = rel_x[i]; A[i] = 0.f; }
    if (tid < R_REL) cnt[tid] = 0.f;
    __syncthreads();

    for (int e = tid; e < ER_REL; e += 1024) {
        int sr = rel_ei[e];
        int dr = rel_ei[ER_REL + e];
        float a = rel_ea[e];
        atomicAdd(&A[dr * R_REL + sr], a);
        atomicAdd(&cnt[dr], 1.0f);
    }
    __syncthreads();

    int r  = tid >> 4;
    int c4 = (tid & 15) * 4;
    float inv = 1.0f / fmaxf(cnt[r], 1.0f);

    #pragma unroll
    for (int it = 0; it < 2; ++it) {
        float4 acc = make_float4(0.f, 0.f, 0.f, 0.f);
        #pragma unroll 8
        for (int k = 0; k < R_REL; ++k) {
            float a = A[r * R_REL + k];
            float4 hv = *(const float4*)&h[k * RF_REL + c4];
            acc.x += a * hv.x; acc.y += a * hv.y;
            acc.z += a * hv.z; acc.w += a * hv.w;
        }
        __syncthreads();
        float4 hv = *(const float4*)&h[r * RF_REL + c4];
        hv.x = fmaxf(hv.x + acc.x * inv, 0.f);
        hv.y = fmaxf(hv.y + acc.y * inv, 0.f);
        hv.z = fmaxf(hv.z + acc.z * inv, 0.f);
        hv.w = fmaxf(hv.w + acc.w * inv, 0.f);
        *(float4*)&h[r * RF_REL + c4] = hv;
        __syncthreads();
    }

    for (int i = tid; i < RF_REL * DIM; i += 1024) A[i] = W_nn[i];
    __syncthreads();
    float4 acc = make_float4(b_nn[c4], b_nn[c4 + 1], b_nn[c4 + 2], b_nn[c4 + 3]);
    #pragma unroll 8
    for (int k = 0; k < RF_REL; ++k) {
        float hv = h[r * RF_REL + k];
        float4 wv = *(const float4*)&A[k * DIM + c4];
        acc.x += hv * wv.x; acc.y += hv * wv.y;
        acc.z += hv * wv.z; acc.w += hv * wv.w;
    }
    *(float4*)&g_wrel[r * DIM + c4] = acc;
}

// x0 = x_in @ fc1 -> fp16 mirror ONLY (fp32 x0 is never read).
// 64-node tiles, 4x4 register tile, swizzled input (R4-proven layout).
__global__ void proj_kernel(const float* __restrict__ x_in,
                            const float* __restrict__ fc1) {
    __shared__ __align__(16) float fs[F_IN * DIM];   // 32 KB
    __shared__ __align__(16) float is[64 * 64];      // 16 KB, swizzled
    int tid = threadIdx.x;
    for (int i = tid; i < F_IN * DIM; i += 256) fs[i] = fc1[i];

    int c4 = (tid & 15) * 4;
    int n4 = (tid >> 4) * 4;
    int sw = tid >> 4;
    int ntiles = (N_NODES + 63) / 64;

    for (int t = blockIdx.x; t < ntiles; t += gridDim.x) {
        int base = t * 64;
        float acc[4][4];
        #pragma unroll
        for (int j = 0; j < 4; ++j)
            #pragma unroll
            for (int i = 0; i < 4; ++i) acc[j][i] = 0.f;

        #pragma unroll
        for (int kb = 0; kb < F_IN; kb += 64) {
            __syncthreads();
            for (int i = tid; i < 64 * 64; i += 256) {
                int nn = i >> 6, k = i & 63;
                int n = base + nn;
                is[nn * 64 + (k ^ (nn >> 2))] =
                    (n < N_NODES) ? x_in[(size_t)n * F_IN + kb + k] : 0.f;
            }
            __syncthreads();
            #pragma unroll 4
            for (int kk = 0; kk < 64; ++kk) {
                float4 f = *(const float4*)&fs[(kb + kk) * DIM + c4];
                int ks = kk ^ sw;
                #pragma unroll
                for (int j = 0; j < 4; ++j) {
                    float iv = is[(n4 + j) * 64 + ks];
                    acc[j][0] += iv * f.x;
                    acc[j][1] += iv * f.y;
                    acc[j][2] += iv * f.z;
                    acc[j][3] += iv * f.w;
                }
            }
        }
        #pragma unroll
        for (int j = 0; j < 4; ++j) {
            int n = base + n4 + j;
            if (n < N_NODES) {
                __half2 h0 = __floats2half2_rn(acc[j][0], acc[j][1]);
                __half2 h1 = __floats2half2_rn(acc[j][2], acc[j][3]);
                uint2 p = make_uint2(*(uint32_t*)&h0, *(uint32_t*)&h1);
                *(uint2*)(g_x0h + (size_t)n * 32 + (c4 >> 1)) = p;
            }
        }
    }
}

// Push edge sweep, 4-edge pipelined: 16-lane group takes 4 consecutive edges,
// indices via two broadcast uint4 loads, 4 gathers in flight before any RED.
__global__ void edge_kernel(const int* __restrict__ dst,
                            int which_x, int count_deg) {
    __shared__ __align__(16) float ws[R_REL * DIM];  // 16 KB
    for (int i = threadIdx.x; i < R_REL * DIM; i += blockDim.x) ws[i] = g_wrel[i];
    __syncthreads();

    const __half2* __restrict__ xh = which_x ? g_x1h : g_x0h;

    int G    = (gridDim.x * blockDim.x) >> 4;                 // total 16-lane groups
    int g    = (blockIdx.x * blockDim.x + threadIdx.x) >> 4;
    int lane = threadIdx.x & 15;
    const int NQUADS = N_EDGES / 4;                           // 500000

    for (int q = g; q < NQUADS; q += G) {
        int e = q * 4;
        uint4 pk = __ldg((const uint4*)(g_pk + e));   // broadcast within group
        uint4 dd = *(const uint4*)(dst + e);          // broadcast within group

        // issue all 4 gathers before consuming any
        uint2 p0 = __ldg((const uint2*)(xh + (size_t)(pk.x >> 6) * 32 + lane * 2));
        uint2 p1 = __ldg((const uint2*)(xh + (size_t)(pk.y >> 6) * 32 + lane * 2));
        uint2 p2 = __ldg((const uint2*)(xh + (size_t)(pk.z >> 6) * 32 + lane * 2));
        uint2 p3 = __ldg((const uint2*)(xh + (size_t)(pk.w >> 6) * 32 + lane * 2));

        unsigned pks[4] = {pk.x, pk.y, pk.z, pk.w};
        unsigned dds[4] = {dd.x, dd.y, dd.z, dd.w};
        uint2    pps[4] = {p0, p1, p2, p3};
        #pragma unroll
        for (int j = 0; j < 4; ++j) {
            float2 f0 = __half22float2(*(__half2*)&pps[j].x);
            float2 f1 = __half22float2(*(__half2*)&pps[j].y);
            float4 wv = *(const float4*)&ws[(pks[j] & 63u) * DIM + lane * 4];
            red_add_v4(g_agg + (size_t)dds[j] * DIM + lane * 4,
                       f0.x * wv.x, f0.y * wv.y, f1.x * wv.z, f1.y * wv.w);
            if (count_deg && lane == 0) red_add_s32(&g_deg[dds[j]], 1);
        }
    }
}

// x_out = tanh(agg / max(deg,1) + b). layer1 -> fp16 mirror only;
// layer2 -> fp32 g_x0 (for out_kernel).
__global__ void finish_kernel(const float* __restrict__ b,
                              int layer, int zero_agg) {
    int i = blockIdx.x * blockDim.x + threadIdx.x;
    if (i >= N_NODES * (DIM / 4)) return;
    int n = i >> 4, c4 = (i & 15) * 4;
    float4 v = ((const float4*)g_agg)[i];
    int d = g_deg[n];
    float inv = 1.0f / (float)(d > 0 ? d : 1);
    float4 bb = *(const float4*)(b + c4);
    v.x = tanhf(v.x * inv + bb.x);
    v.y = tanhf(v.y * inv + bb.y);
    v.z = tanhf(v.z * inv + bb.z);
    v.w = tanhf(v.w * inv + bb.w);
    if (layer == 1) {
        __half2 h0 = __floats2half2_rn(v.x, v.y);
        __half2 h1 = __floats2half2_rn(v.z, v.w);
        uint2 p = make_uint2(*(uint32_t*)&h0, *(uint32_t*)&h1);
        *(uint2*)(g_x1h + (size_t)n * 32 + (c4 >> 1)) = p;
    } else {
        ((float4*)g_x0)[i] = v;
    }
    if (zero_agg) ((float4*)g_agg)[i] = make_float4(0.f, 0.f, 0.f, 0.f);
}

// out = x2 @ fc2_w + fc2_b   (x2 in g_x0).  16 nodes per block.
__global__ void out_kernel(const float* __restrict__ fc2w,
                           const float* __restrict__ fc2b,
                           float* __restrict__ out) {
    __shared__ float ws[DIM * NCLS];
    __shared__ float xs[16 * DIM];
    int tid = threadIdx.x;
    for (int i = tid; i < DIM * NCLS; i += 256) ws[i] = fc2w[i];
    int base = blockIdx.x * 16;
    for (int i = tid; i < 16 * DIM; i += 256) xs[i] = g_x0[(size_t)base * DIM + i];
    __syncthreads();
    int nl = tid >> 4, k = tid & 15;
    float acc = fc2b[k];
    #pragma unroll
    for (int c = 0; c < DIM; ++c)
        acc += xs[nl * DIM + c] * ws[c * NCLS + k];
    out[(size_t)(base + nl) * NCLS + k] = acc;
}

// ---------------- launch ----------------
extern "C" void kernel_launch(void* const* d_in, const int* in_sizes, int n_in,
                              void* d_out, int out_size) {
    const float* x_in   = (const float*)d_in[0];
    const float* rel_x  = (const float*)d_in[1];
    const int*   ei     = (const int*)  d_in[2];
    const int*   et     = (const int*)  d_in[3];
    const int*   rel_ei = (const int*)  d_in[4];
    const float* rel_ea = (const float*)d_in[5];
    const float* fc1    = (const float*)d_in[6];
    const float* W_nn   = (const float*)d_in[7];
    const float* b_nn   = (const float*)d_in[8];
    const float* b1     = (const float*)d_in[9];
    const float* b2     = (const float*)d_in[10];
    const float* fc2w   = (const float*)d_in[11];
    const float* fc2b   = (const float*)d_in[12];
    float* out = (float*)d_out;

    zero_kernel<<<(N_NODES * DIM / 4 + 255) / 256, 256>>>();
    pack_kernel<<<(N_EDGES + 255) / 256, 256>>>(ei, et);
    rel_kernel<<<1, 1024>>>(rel_x, rel_ei, rel_ea, W_nn, b_nn);
    proj_kernel<<<1184, 256>>>(x_in, fc1);

    // conv1
    edge_kernel<<<2048, 256>>>(ei + N_EDGES, /*which_x=*/0, /*count_deg=*/1);
    finish_kernel<<<(N_NODES * 16 + 255) / 256, 256>>>(b1, 1, /*zero_agg=*/1);

    // conv2
    edge_kernel<<<2048, 256>>>(ei + N_EDGES, /*which_x=*/1, /*count_deg=*/0);
    finish_kernel<<<(N_NODES * 16 + 255) / 256, 256>>>(b2, 2, /*zero_agg=*/0);

    out_kernel<<<N_NODES / 16, 256>>>(fc2w, fc2b, out);
}